// round 4
// baseline (speedup 1.0000x reference)
#include <cuda_runtime.h>
#include <cuda_bf16.h>

// YOLO loss, restructured:
//   loss[b] = sum_rc has[b,rc] * A[rc] + B0
// where A[rc] = 5*(X+Y+W+H)[rc] + 0.5*Cmse[rc]  (batch-reduced per cell)
//       B0    = sum_rc (0.5*Cmse + class_mse)[rc]
//
// pass1: streaming batch reduction (HBM-bound, 192.7MB) -> A[49], B, has[b][rc]
// pass2: per-b 49-dot (3.2MB)

#define SGRID 7
#define DCH 30
#define NBATCH 16384
#define NCELLS (NBATCH * SGRID * SGRID)   // 802816
#define TILE 128                          // cells per block (== block threads)

__device__ float g_A[49];
__device__ float g_B;
__device__ float g_has[NCELLS];

__device__ __forceinline__ float scalar_val(const void* p) {
    if (!p) return 448.0f;
    int iv = *(const int*)p;
    if (iv > 0 && iv < 1000000) return (float)iv;          // int32 scalar
    float fv = __int_as_float(iv);
    if (fv > 0.0f && fv < 1000000.0f) return fv;           // float32 scalar
    return 448.0f;
}

__global__ void init_kernel() {
    int t = threadIdx.x;
    if (t < 49) g_A[t] = 0.0f;
    if (t == 49) g_B = 0.0f;
}

__device__ __forceinline__ float iou_tinv(
    float px, float py, float pw, float ph,
    float tx, float ty, float tw, float th,
    float cw, float ch)
{
    // translation-invariant: drop common (rows,cols)*cell offsets
    float acx = px * cw, acy = py * ch;
    float bcx = tx * cw, bcy = ty * ch;
    float ax0 = acx - pw * 0.5f, ax1 = acx + pw * 0.5f;
    float ay0 = acy - ph * 0.5f, ay1 = acy + ph * 0.5f;
    float bx0 = bcx - tw * 0.5f, bx1 = bcx + tw * 0.5f;
    float by0 = bcy - th * 0.5f, by1 = bcy + th * 0.5f;
    float iw = fmaxf(fminf(ax1, bx1) - fmaxf(ax0, bx0), 0.0f);
    float ih = fmaxf(fminf(ay1, by1) - fmaxf(ay0, by0), 0.0f);
    float inter = iw * ih;
    float aa = (ax1 - ax0) * (ay1 - ay0);
    float ab = (bx1 - bx0) * (by1 - by0);
    return inter / (aa + ab - inter + 1e-9f);
}

__global__ __launch_bounds__(TILE) void pass1_kernel(
    const float* __restrict__ outp,
    const float* __restrict__ tgtp,
    const void* __restrict__ wp,
    const void* __restrict__ hp)
{
    __shared__ float s_out[TILE * DCH];
    __shared__ float s_tgt[TILE * DCH];
    __shared__ float s_A[49];
    __shared__ float s_Bw[TILE / 32];

    const int tid  = threadIdx.x;
    const int tile = blockIdx.x;

    // coalesced float4 staging: TILE*DCH floats = 960 float4 per tensor
    const int NV4 = TILE * DCH / 4;
    const float4* go = (const float4*)(outp) + (size_t)tile * NV4;
    const float4* gt = (const float4*)(tgtp) + (size_t)tile * NV4;
    float4* so4 = (float4*)s_out;
    float4* st4 = (float4*)s_tgt;
    for (int i = tid; i < NV4; i += TILE) {
        so4[i] = go[i];
        st4[i] = gt[i];
    }
    if (tid < 49) s_A[tid] = 0.0f;
    __syncthreads();

    const float W = scalar_val(wp);
    const float H = scalar_val(hp);
    const float cw = W / 7.0f;
    const float ch = H / 7.0f;

    // per-cell compute from smem (float2 reads; cell base = tid*30 floats)
    const float2* o2 = (const float2*)s_out + tid * (DCH / 2);
    const float2* t2 = (const float2*)s_tgt + tid * (DCH / 2);

    float2 o01 = o2[0];   // ch0,1
    float2 o23 = o2[1];   // ch2,3
    float2 o45 = o2[2];   // ch4,5
    float2 o67 = o2[3];   // ch6,7
    float2 o89 = o2[4];   // ch8,9
    float2 tt01 = t2[0];
    float2 tt23 = t2[1];
    float2 tt45 = t2[2];

    float tx = tt01.x, ty = tt01.y;
    float tw = tt23.x * W, th = tt23.y * H;
    float has = tt45.x;                       // ch4 == t_conf == has

    // predictor 0: px=ch0 py=ch1 pw=ch3*W ph=ch4*H conf=ch4
    float iou0 = iou_tinv(o01.x, o01.y, o23.y * W, o45.x * H, tx, ty, tw, th, cw, ch);
    // predictor 1: px=ch5 py=ch6 pw=ch8*W ph=ch9*H conf=ch9
    float iou1 = iou_tinv(o45.y, o67.x, o89.x * W, o89.y * H, tx, ty, tw, th, cw, ch);

    // best = last argmax on ties: best=1 iff iou1 >= iou0
    float best_conf = (iou1 >= iou0) ? o89.y : o45.x;

    // loss predictor L = P-1 = 1
    float dx = tx - o45.y;
    float dy = ty - o67.x;
    float xy = dx * dx + dy * dy;
    float dw = sqrtf(tw) - sqrtf(o89.x * W);
    float dh = sqrtf(th) - sqrtf(o89.y * H);
    float wh = dw * dw + dh * dh;
    float dc = has - o89.y;                   // t_conf - p_conf (p_conf = ch9)
    float cm = dc * dc;

    float Acon = 5.0f * (xy + wh) + 0.5f * cm;
    float Bcon = 0.5f * cm;

    #pragma unroll
    for (int k = 0; k < 10; k++) {            // class channels 10..29 as float2
        float2 tc = t2[5 + k];
        float2 oc = o2[5 + k];
        float d1 = tc.x - oc.x * best_conf;
        float d2 = tc.y - oc.y * best_conf;
        Bcon += d1 * d1 + d2 * d2;
    }

    int cellIdx = tile * TILE + tid;
    int rc = cellIdx % 49;
    g_has[cellIdx] = has;

    atomicAdd(&s_A[rc], Acon);

    // block reduce Bcon
    #pragma unroll
    for (int off = 16; off > 0; off >>= 1)
        Bcon += __shfl_xor_sync(0xFFFFFFFFu, Bcon, off);
    if ((tid & 31) == 0) s_Bw[tid >> 5] = Bcon;
    __syncthreads();

    if (tid == 0) {
        float b = 0.0f;
        #pragma unroll
        for (int w = 0; w < TILE / 32; w++) b += s_Bw[w];
        atomicAdd(&g_B, b);
    }
    if (tid < 49) atomicAdd(&g_A[tid], s_A[tid]);
}

__global__ __launch_bounds__(256) void pass2_kernel(float* __restrict__ lossout) {
    __shared__ float sA[49];
    __shared__ float sB;
    if (threadIdx.x < 49) sA[threadIdx.x] = g_A[threadIdx.x];
    if (threadIdx.x == 49) sB = g_B;
    __syncthreads();

    int b = blockIdx.x * blockDim.x + threadIdx.x;
    if (b >= NBATCH) return;
    const float* hb = g_has + (size_t)b * 49;
    float acc = sB;
    #pragma unroll
    for (int i = 0; i < 49; i++)
        acc = fmaf(hb[i], sA[i], acc);
    lossout[b] = acc;
}

extern "C" void kernel_launch(void* const* d_in, const int* in_sizes, int n_in,
                              void* d_out, int out_size) {
    const float* outp = (const float*)d_in[0];
    const float* tgtp = (const float*)d_in[1];
    const void* wp = (n_in > 2) ? d_in[2] : nullptr;
    const void* hp = (n_in > 3) ? d_in[3] : nullptr;
    float* loss = (float*)d_out;

    init_kernel<<<1, 64>>>();
    pass1_kernel<<<NCELLS / TILE, TILE>>>(outp, tgtp, wp, hp);
    pass2_kernel<<<(NBATCH + 255) / 256, 256>>>(loss);
}

// round 17
// speedup vs baseline: 1.1244x; 1.1244x over previous
#include <cuda_runtime.h>
#include <cuda_bf16.h>

// YOLO loss, restructured:
//   loss[b] = sum_rc has[b,rc] * A[rc] + B0
// where A[rc] = 5*(X+Y+W+H)[rc] + 0.5*Cmse[rc]  (batch-reduced per cell)
//       B0    = sum_rc (0.5*Cmse + class_mse)[rc]
//
// kernel1 (pass1): persistent streaming batch reduction -> g_A[49], g_B, g_has
// kernel2 (pass2): per-b 49-dot; self-cleans g_A/g_B for the next graph replay.

#define SGRID 7
#define DCH 30
#define NBATCH 16384
#define NCELLS (NBATCH * SGRID * SGRID)   // 802816
#define TILE 128                          // cells per tile (== block threads)
#define NTILES (NCELLS / TILE)            // 6272
#define GRID1 896                         // 6272 / 896 = 7 tiles per block exactly
#define P2BLOCKS (NBATCH / 256)           // 64

__device__ float g_A[49];
__device__ float g_B;
__device__ float g_has[NCELLS];
__device__ int   g_cnt2;                  // pass2 cleanup counter (self-resetting)

__device__ __forceinline__ float scalar_val(const void* p) {
    if (!p) return 448.0f;
    int iv = *(const int*)p;
    if (iv > 0 && iv < 1000000) return (float)iv;          // int32 scalar
    float fv = __int_as_float(iv);
    if (fv > 0.0f && fv < 1000000.0f) return fv;           // float32 scalar
    return 448.0f;
}

__device__ __forceinline__ float iou_tinv(
    float px, float py, float pw, float ph,
    float tx, float ty, float tw, float th,
    float cw, float ch)
{
    // translation-invariant: drop common (rows,cols)*cell offsets
    float acx = px * cw, acy = py * ch;
    float bcx = tx * cw, bcy = ty * ch;
    float ax0 = acx - pw * 0.5f, ax1 = acx + pw * 0.5f;
    float ay0 = acy - ph * 0.5f, ay1 = acy + ph * 0.5f;
    float bx0 = bcx - tw * 0.5f, bx1 = bcx + tw * 0.5f;
    float by0 = bcy - th * 0.5f, by1 = bcy + th * 0.5f;
    float iw = fmaxf(fminf(ax1, bx1) - fmaxf(ax0, bx0), 0.0f);
    float ih = fmaxf(fminf(ay1, by1) - fmaxf(ay0, by0), 0.0f);
    float inter = iw * ih;
    float aa = (ax1 - ax0) * (ay1 - ay0);
    float ab = (bx1 - bx0) * (by1 - by0);
    return inter / (aa + ab - inter + 1e-9f);
}

__global__ __launch_bounds__(TILE) void pass1_kernel(
    const float* __restrict__ outp,
    const float* __restrict__ tgtp,
    const void* __restrict__ wp,
    const void* __restrict__ hp)
{
    __shared__ float s_out[TILE * DCH];
    __shared__ float s_tgt[TILE * DCH];
    __shared__ float s_A[49];
    __shared__ float s_Bw[TILE / 32];

    const int tid = threadIdx.x;

    if (tid < 49) s_A[tid] = 0.0f;

    const float W = scalar_val(wp);
    const float H = scalar_val(hp);
    const float cw = W / 7.0f;
    const float ch = H / 7.0f;

    const int NV4 = TILE * DCH / 4;       // 960 float4 per tensor per tile
    float4* so4 = (float4*)s_out;
    float4* st4 = (float4*)s_tgt;
    const float2* o2 = (const float2*)s_out + tid * (DCH / 2);
    const float2* t2 = (const float2*)s_tgt + tid * (DCH / 2);

    float Bacc = 0.0f;                    // per-thread B accumulator across tiles

    for (int tile = blockIdx.x; tile < NTILES; tile += GRID1) {
        // coalesced float4 staging
        const float4* go = (const float4*)(outp) + (size_t)tile * NV4;
        const float4* gt = (const float4*)(tgtp) + (size_t)tile * NV4;
        #pragma unroll
        for (int i = 0; i < NV4 / TILE; i++) {          // 7 full rounds
            so4[tid + i * TILE] = go[tid + i * TILE];
            st4[tid + i * TILE] = gt[tid + i * TILE];
        }
        {   // remainder round (960 = 7*128 + 64)
            int i = tid + (NV4 / TILE) * TILE;
            if (i < NV4) { so4[i] = go[i]; st4[i] = gt[i]; }
        }
        __syncthreads();

        float2 o01 = o2[0];   // ch0,1
        float2 o23 = o2[1];   // ch2,3
        float2 o45 = o2[2];   // ch4,5
        float2 o67 = o2[3];   // ch6,7
        float2 o89 = o2[4];   // ch8,9
        float2 tt01 = t2[0];
        float2 tt23 = t2[1];
        float2 tt45 = t2[2];

        float tx = tt01.x, ty = tt01.y;
        float tw = tt23.x * W, th = tt23.y * H;
        float has = tt45.x;                   // ch4 == t_conf == has

        // predictor 0: px=ch0 py=ch1 pw=ch3*W ph=ch4*H conf=ch4
        float iou0 = iou_tinv(o01.x, o01.y, o23.y * W, o45.x * H, tx, ty, tw, th, cw, ch);
        // predictor 1: px=ch5 py=ch6 pw=ch8*W ph=ch9*H conf=ch9
        float iou1 = iou_tinv(o45.y, o67.x, o89.x * W, o89.y * H, tx, ty, tw, th, cw, ch);

        // best = last argmax on ties: best=1 iff iou1 >= iou0
        float best_conf = (iou1 >= iou0) ? o89.y : o45.x;

        // loss predictor L = P-1 = 1
        float dx = tx - o45.y;
        float dy = ty - o67.x;
        float xy = dx * dx + dy * dy;
        float dw = sqrtf(tw) - sqrtf(o89.x * W);
        float dh = sqrtf(th) - sqrtf(o89.y * H);
        float wh = dw * dw + dh * dh;
        float dc = has - o89.y;               // t_conf - p_conf (p_conf = ch9)
        float cm = dc * dc;

        float Acon = 5.0f * (xy + wh) + 0.5f * cm;
        float Bcon = 0.5f * cm;

        #pragma unroll
        for (int k = 0; k < 10; k++) {        // class channels 10..29 as float2
            float2 tc = t2[5 + k];
            float2 oc = o2[5 + k];
            float d1 = tc.x - oc.x * best_conf;
            float d2 = tc.y - oc.y * best_conf;
            Bcon += d1 * d1 + d2 * d2;
        }

        int cellIdx = tile * TILE + tid;
        g_has[cellIdx] = has;
        atomicAdd(&s_A[cellIdx % 49], Acon);
        Bacc += Bcon;

        __syncthreads();                      // protect smem before next tile's stores
    }

    // block-level B reduce, then ONE global atomic per block
    #pragma unroll
    for (int off = 16; off > 0; off >>= 1)
        Bacc += __shfl_xor_sync(0xFFFFFFFFu, Bacc, off);
    if ((tid & 31) == 0) s_Bw[tid >> 5] = Bacc;
    __syncthreads();

    if (tid == 0) {
        float b = 0.0f;
        #pragma unroll
        for (int w = 0; w < TILE / 32; w++) b += s_Bw[w];
        atomicAdd(&g_B, b);
    }
    if (tid < 49) atomicAdd(&g_A[tid], s_A[tid]);
}

__global__ __launch_bounds__(256) void pass2_kernel(float* __restrict__ lossout) {
    __shared__ float sA[49];
    __shared__ float sB;
    __shared__ int s_last;
    if (threadIdx.x < 49) sA[threadIdx.x] = g_A[threadIdx.x];
    if (threadIdx.x == 49) sB = g_B;
    __syncthreads();

    // self-clean: once every block has snapshotted g_A/g_B, last block zeroes them
    if (threadIdx.x == 0) {
        __threadfence();
        int old = atomicAdd(&g_cnt2, 1);
        s_last = (old == P2BLOCKS - 1) ? 1 : 0;
    }
    __syncthreads();
    if (s_last) {
        if (threadIdx.x < 49) g_A[threadIdx.x] = 0.0f;
        if (threadIdx.x == 49) g_B = 0.0f;
        if (threadIdx.x == 50) g_cnt2 = 0;
    }

    int b = blockIdx.x * blockDim.x + threadIdx.x;
    if (b >= NBATCH) return;
    const float* hb = g_has + (size_t)b * 49;
    float acc = sB;
    #pragma unroll
    for (int i = 0; i < 49; i++)
        acc = fmaf(hb[i], sA[i], acc);
    lossout[b] = acc;
}

extern "C" void kernel_launch(void* const* d_in, const int* in_sizes, int n_in,
                              void* d_out, int out_size) {
    const float* outp = (const float*)d_in[0];
    const float* tgtp = (const float*)d_in[1];
    const void* wp = (n_in > 2) ? d_in[2] : nullptr;
    const void* hp = (n_in > 3) ? d_in[3] : nullptr;
    float* loss = (float*)d_out;

    pass1_kernel<<<GRID1, TILE>>>(outp, tgtp, wp, hp);
    pass2_kernel<<<P2BLOCKS, 256>>>(loss);
}